// round 16
// baseline (speedup 1.0000x reference)
#include <cuda_runtime.h>

#define BLK 256
#define NCHUNK 24

// byte offsets in dynamic smem
#define SCAT 0        // cat tf32: [24 k][184 bm-pad] u32 = 17664 B
#define SWF  17664    // Wfrag: [2 par][2 mt][3 ks][32 lane][4 r] u32 = 6144 B
#define SX2  23808    // xrow: [24][11][16] f32 = 16896 B
#define SCG  40704    // cgs: 1332 f32 = 5328 B
#define SX1  46032    // xcol: [2][11][16] f32 = 1408 B (double-buffered)
#define SAS  47440    // As: ull[121][8] = 7744 B
#define SMEM_BYTES 55184

typedef unsigned long long ull;
typedef unsigned int u32;

// per-l transposed W scratch (d-major within each pair block)
__device__ float g_Wt[2045952];

__device__ __forceinline__ ull pack2(float v) {
    ull r; asm("mov.b64 %0, {%1, %1};" : "=l"(r) : "f"(v)); return r;
}
__device__ __forceinline__ ull mul2(ull a, ull b) {
    ull r; asm("mul.rn.f32x2 %0, %1, %2;" : "=l"(r) : "l"(a), "l"(b)); return r;
}
__device__ __forceinline__ ull fma2(ull a, ull b, ull c) {
    ull r; asm("fma.rn.f32x2 %0, %1, %2, %3;" : "=l"(r) : "l"(a), "l"(b), "l"(c)); return r;
}
__device__ __forceinline__ void unpack2(ull v, float& lo, float& hi) {
    asm("mov.b64 {%0, %1}, %2;" : "=f"(lo), "=f"(hi) : "l"(v));
}
__device__ __forceinline__ u32 tf32c(float f) {
    u32 r; asm("cvt.rna.tf32.f32 %0, %1;" : "=r"(r) : "f"(f)); return r;
}
__device__ __forceinline__ ull packu(u32 lo, u32 hi) {
    ull r; asm("mov.b64 %0, {%1, %2};" : "=l"(r) : "r"(lo), "r"(hi)); return r;
}

#define MMA_TF32(d, a, bb0, bb1) \
    asm volatile("mma.sync.aligned.m16n8k8.row.col.f32.tf32.tf32.f32 " \
        "{%0,%1,%2,%3}, {%4,%5,%6,%7}, {%8,%9}, {%0,%1,%2,%3};" \
        : "+f"((d)[0]), "+f"((d)[1]), "+f"((d)[2]), "+f"((d)[3]) \
        : "r"((a)[0]), "r"((a)[1]), "r"((a)[2]), "r"((a)[3]), "r"(bb0), "r"(bb1))

__device__ __forceinline__ const float* pick6(
    const float* a0, const float* a1, const float* a2,
    const float* a3, const float* a4, const float* a5, int l) {
    switch (l) {
        case 0: return a0; case 1: return a1; case 2: return a2;
        case 3: return a3; case 4: return a4; default: return a5;
    }
}

// fragment slot (u32 index) for W element (h 0..31, k 0..23) in buffer par
__device__ __forceinline__ int wfrag_idx(int par, int h, int k) {
    const int mt = h >> 4;
    const int hh = h & 15;
    const int lane = (hh & 7) * 4 + (k & 3);
    const int r = ((k >> 2) & 1) * 2 + (hh >> 3);
    return (((par * 2 + mt) * 3 + (k >> 3)) * 32 + lane) * 4 + r;
}

template <int N>
__device__ __forceinline__ void run_pair(
    const float* __restrict__ Xc, char* smem,
    const float* __restrict__ Wl, int KIN, int koff,
    int nrow, int nchk, int sj, int cbase,
    float* __restrict__ out, int b0, int moff)
{
    constexpr int NT = 2 * N;        // number of n8 tiles over bm = 16*N
    constexpr int MS = (N + 3) / 4;
    const int tid  = threadIdx.x;
    const int lane = tid & 31;
    const int w    = tid >> 5;       // warp 0..7 (= k-group in cat build)
    const int bp   = tid & 7;        // batch pair lane (f32x2)
    const int rr   = tid >> 3;
    const int ms2  = rr & 3;         // mi slice in cat build
    const int mt     = w & 1;        // m16 tile over h (0..1)
    const int ntbase = w >> 1;       // n-tile base (stride 4)

    u32*  __restrict__ catT = (u32*)(smem + SCAT);
    u32*  __restrict__ WfU  = (u32*)(smem + SWF);
    const ull* __restrict__ xr64 = (const ull*)(smem + SX2);
    const ull* __restrict__ xc64 = (const ull*)(smem + SX1);
    const float* __restrict__ cgs = (const float*)(smem + SCG);
    float* __restrict__ xcol = (float*)(smem + SX1);
    ull* __restrict__ As = (ull*)(smem + SAS);
    const unsigned nchku = (unsigned)nchk;
    const int xcstride = 24 * nchk;
    const int sd = 12 - sj;

    float acc[6][4];
#pragma unroll
    for (int j = 0; j < 6; ++j)
#pragma unroll
        for (int r = 0; r < 4; ++r) acc[j][r] = 0.f;

#pragma unroll 1
    for (int cc = 0; cc < NCHUNK; ++cc) {
        const int par = cc & 1;
        // ---- phase 1: W -> Wfrag[par] (fragment order), A build, xcol staging ----
#pragma unroll
        for (int t = 0; t < 2; ++t) {
            const int i = tid + 256 * t;
            if (i < 384) {                       // 32 h x 12 float2
                const int h  = i / 12;
                const int kp = i - h * 12;
                const float2 wv = *reinterpret_cast<const float2*>(
                    Wl + h * KIN + koff + cc * 24 + kp * 2);
                WfU[wfrag_idx(par, h, kp * 2)]     = tf32c(wv.x);
                WfU[wfrag_idx(par, h, kp * 2 + 1)] = tf32c(wv.y);
            }
        }
        // A[mi][j][bp] = cg[mi; j (loop idx), der (chunk idx)] * xcol[cc][der][bp]
#pragma unroll
        for (int t = 0; t < 4; ++t) {
            const int s = rr + 32 * t;
            if (s < 121) {
                const int mi = s / 11;
                const int j  = s - mi * 11;
                if (j < nrow) {
                    const int der = mi + cbase - j;
                    const bool ok = ((unsigned)der < nchku);
                    const int dc = ok ? der : 0;
                    const float cgv = ok ? cgs[mi * 121 + j * sj + dc * sd] : 0.f;
                    const ull  xv  = xc64[par * 88 + dc * 8 + bp];
                    As[s * 8 + bp] = ok ? mul2(pack2(cgv), xv) : 0ull;
                }
            }
        }
        if (cc + 1 < NCHUNK && tid < 16 * nchk) {
            const int m = tid >> 4;
            const int b = tid & 15;
            xcol[(par ^ 1) * 176 + m * 16 + b] =
                Xc[(b0 + b) * xcstride + (cc + 1) * nchk + m];
        }
        __syncthreads();
        // ---- phase 2: cat build -> tf32 [k][bm], k=w*3+jj; loop = min(n1,n2) ----
        {
            ull bacc[3][MS];
#pragma unroll
            for (int j = 0; j < 3; ++j)
#pragma unroll
                for (int mj = 0; mj < MS; ++mj) bacc[j][mj] = 0ull;
#pragma unroll
            for (int j = 0; j < 11; ++j) {
                if (j >= nrow) break;             // CTA-uniform
                ull a[MS];
#pragma unroll
                for (int mj = 0; mj < MS; ++mj) {
                    const int mi = ms2 + 4 * mj;
                    if (mi < N) a[mj] = As[(mi * 11 + j) * 8 + bp];
                }
#pragma unroll
                for (int jj = 0; jj < 3; ++jj) {
                    const ull xv = xr64[(w * 3 + jj) * 88 + j * 8 + bp];
#pragma unroll
                    for (int mj = 0; mj < MS; ++mj) {
                        const int mi = ms2 + 4 * mj;
                        if (mi < N) bacc[jj][mj] = fma2(a[mj], xv, bacc[jj][mj]);
                    }
                }
            }
#pragma unroll
            for (int jj = 0; jj < 3; ++jj) {
                const int k = w * 3 + jj;
#pragma unroll
                for (int mj = 0; mj < MS; ++mj) {
                    const int mi = ms2 + 4 * mj;
                    if (mi < N) {
                        float lo, hi;
                        unpack2(bacc[jj][mj], lo, hi);
                        *reinterpret_cast<ull*>(catT + k * 184 + mi * 16 + 2 * bp) =
                            packu(tf32c(lo), tf32c(hi));
                    }
                }
            }
        }
        __syncthreads();
        // ---- phase 3: tf32 MMA GEMM ----
#pragma unroll
        for (int ks = 0; ks < 3; ++ks) {
            const uint4 av = *reinterpret_cast<const uint4*>(
                WfU + (((par * 2 + mt) * 3 + ks) * 32 + lane) * 4);
            u32 a[4] = { av.x, av.y, av.z, av.w };
            const int kr = ks * 8 + (lane & 3);
#pragma unroll
            for (int j = 0; j < 6; ++j) {
                const int nt = ntbase + 4 * j;
                if (nt < NT) {                    // warp-uniform
                    const int cb = nt * 8 + (lane >> 2);
                    const u32 b0v = catT[kr * 184 + cb];
                    const u32 b1v = catT[(kr + 4) * 184 + cb];
                    MMA_TF32(acc[j], a, b0v, b1v);
                }
            }
        }
        __syncthreads();   // restored: rally point before next chunk's phase 1
    }

    // ---- epilogue: fragments -> atomicAdd ----
#pragma unroll
    for (int j = 0; j < 6; ++j) {
        const int nt = ntbase + 4 * j;
        if (nt < NT) {
            const int hrow = mt * 16 + (lane >> 2);
            const int cb   = nt * 8 + 2 * (lane & 3);
#pragma unroll
            for (int r = 0; r < 4; ++r) {
                const int h  = hrow + ((r >> 1) << 3);
                const int bm = cb + (r & 1);
                const int b  = bm & 15;
                const int mi = bm >> 4;
                atomicAdd(out + (u32)(b0 + b) * 1152 + h * 36 + moff + mi, acc[j][r]);
            }
        }
    }
}

__global__ void __launch_bounds__(BLK, 4) cg_main(
    const float* __restrict__ X0, const float* __restrict__ X1, const float* __restrict__ X2,
    const float* __restrict__ X3, const float* __restrict__ X4, const float* __restrict__ X5,
    const float* __restrict__ W0, const float* __restrict__ W1, const float* __restrict__ W2,
    const float* __restrict__ W3, const float* __restrict__ W4, const float* __restrict__ W5,
    const float* __restrict__ cg, float* __restrict__ out)
{
    extern __shared__ char smem[];

    const int item = blockIdx.x >> 4;
    const int b0   = (blockIdx.x & 15) << 4;
    const int tid  = threadIdx.x;

    // decode work item: l ordered 5,4,3,2,1,0
    int l = 0, l1 = 0, l2 = 0, pidx = 0;
    {
        int cur = 0;
        bool done = false;
        for (int oi = 0; oi < 6 && !done; ++oi) {
            int L = 5 - oi;
            int pi = 0;
            for (int a = 0; a <= 5 && !done; ++a) {
                for (int b2 = 0; b2 <= 5; ++b2) {
                    int dd = a - b2; if (dd < 0) dd = -dd;
                    if (dd <= L && L <= a + b2) {
                        if (cur == item) { l = L; l1 = a; l2 = b2; pidx = pi; done = true; break; }
                        ++cur; ++pi;
                    }
                }
            }
        }
    }

    const int n1 = 2 * l1 + 1, n2 = 2 * l2 + 1, n = 2 * l + 1;
    int KIN, moff, woff;
    switch (l) {
        case 0: KIN = 3456;  moff = 0;  woff = 0;       break;
        case 1: KIN = 8640;  moff = 1;  woff = 110592;  break;
        case 2: KIN = 12096; moff = 4;  woff = 387072;  break;
        case 3: KIN = 13824; moff = 9;  woff = 774144;  break;
        case 4: KIN = 13824; moff = 16; woff = 1216512; break;
        default: KIN = 12096; moff = 25; woff = 1658880; break;
    }
    const float* Xa = pick6(X0, X1, X2, X3, X4, X5, l1);
    const float* Xb = pick6(X0, X1, X2, X3, X4, X5, l2);
    const float* Wl = pick6(W0, W1, W2, W3, W4, W5, l);
    const int koff = pidx * 576;

    // orientation: chunk side = larger n; row side (phase-2 loop) = min n.
    const int swap = (n2 > n1) ? 1 : 0;
    const float* Xrow = swap ? Xa : Xb;
    const float* Xchk = swap ? Xb : Xa;
    const int nrow = swap ? n1 : n2;
    const int nchk = swap ? n2 : n1;
    const int sj   = swap ? 11 : 1;
    const float* Wsel = swap ? (g_Wt + woff) : Wl;

    // row-side x tile: global (b,ch,m) -> smem [ch][m][b16]
    float* xrs = (float*)(smem + SX2);
    for (int i = tid; i < 16 * 24 * nrow; i += BLK) {
        int b = i / (24 * nrow);
        int r = i - b * 24 * nrow;
        int d = r / nrow;
        int m = r - d * nrow;
        xrs[(d * 11 + m) * 16 + b] = Xrow[(b0 + b) * 24 * nrow + r];
    }
    // cg slab
    float* cgs = (float*)(smem + SCG);
    const float* cgp = cg + ((l1 * 6 + l2) * 6 + l) * 1331;
    for (int i = tid; i < n * 121; i += BLK) cgs[i] = cgp[i];
    // chunk-side column cc=0 into buffer 0
    float* xcol = (float*)(smem + SX1);
    if (tid < 16 * nchk) {
        const int m = tid >> 4;
        const int b = tid & 15;
        xcol[m * 16 + b] = Xchk[(b0 + b) * (24 * nchk) + m];
    }
    __syncthreads();

    const int cbase = l1 + l2 - l;
    switch (l) {
        case 0: run_pair<1>(Xchk, smem, Wsel, KIN, koff, nrow, nchk, sj, cbase, out, b0, moff); break;
        case 1: run_pair<3>(Xchk, smem, Wsel, KIN, koff, nrow, nchk, sj, cbase, out, b0, moff); break;
        case 2: run_pair<5>(Xchk, smem, Wsel, KIN, koff, nrow, nchk, sj, cbase, out, b0, moff); break;
        case 3: run_pair<7>(Xchk, smem, Wsel, KIN, koff, nrow, nchk, sj, cbase, out, b0, moff); break;
        case 4: run_pair<9>(Xchk, smem, Wsel, KIN, koff, nrow, nchk, sj, cbase, out, b0, moff); break;
        default: run_pair<11>(Xchk, smem, Wsel, KIN, koff, nrow, nchk, sj, cbase, out, b0, moff); break;
    }
}

// single-kernel W transpose for all 6 l's:
// Wt[h][p*576+d*24+c] = W[h][p*576+c*24+d]
__global__ void wtrans_all(
    const float* __restrict__ W0, const float* __restrict__ W1, const float* __restrict__ W2,
    const float* __restrict__ W3, const float* __restrict__ W4, const float* __restrict__ W5)
{
    const int gi = blockIdx.x * 256 + threadIdx.x;
    if (gi >= 2045952) return;
    int l, base;
    if      (gi < 110592)  { l = 0; base = 0; }
    else if (gi < 387072)  { l = 1; base = 110592; }
    else if (gi < 774144)  { l = 2; base = 387072; }
    else if (gi < 1216512) { l = 3; base = 774144; }
    else if (gi < 1658880) { l = 4; base = 1216512; }
    else                   { l = 5; base = 1658880; }
    const int KIN = (l == 0) ? 3456 : (l == 1) ? 8640 : (l == 2) ? 12096
                  : (l == 3) ? 13824 : (l == 4) ? 13824 : 12096;
    const float* src = pick6(W0, W1, W2, W3, W4, W5, l);
    const int i = gi - base;
    const int h = i / KIN;
    const int t = i - h * KIN;
    const int p = t / 576;
    const int q = t - p * 576;
    const int d = q / 24;
    const int c = q - d * 24;
    g_Wt[gi] = src[h * KIN + p * 576 + c * 24 + d];
}

__global__ void zero_out_kernel(float* __restrict__ o, int nTot) {
    int i = blockIdx.x * 256 + threadIdx.x;
    if (i < nTot) o[i] = 0.f;
}

extern "C" void kernel_launch(void* const* d_in, const int* in_sizes, int n_in,
                              void* d_out, int out_size)
{
    const float* X[6];
    const float* W[6];
    for (int i = 0; i < 6; ++i) X[i] = (const float*)d_in[i];
    for (int i = 0; i < 6; ++i) W[i] = (const float*)d_in[6 + i];
    const float* cg = (const float*)d_in[12];
    float* out = (float*)d_out;

    const int nTot = 256 * 32 * 36;  // 294912
    zero_out_kernel<<<(nTot + 255) / 256, 256>>>(out, nTot);

    wtrans_all<<<(2045952 + 255) / 256, 256>>>(W[0], W[1], W[2], W[3], W[4], W[5]);

    cudaFuncSetAttribute(cg_main, cudaFuncAttributeMaxDynamicSharedMemorySize, SMEM_BYTES);
    cg_main<<<111 * 16, BLK, SMEM_BYTES>>>(
        X[0], X[1], X[2], X[3], X[4], X[5],
        W[0], W[1], W[2], W[3], W[4], W[5],
        cg, out);
}

// round 17
// speedup vs baseline: 1.0873x; 1.0873x over previous
#include <cuda_runtime.h>

#define BLK 256
#define NCHUNK 24

// byte offsets in dynamic smem
#define SCAT 0        // cat tf32: [24 k][184 bm-pad] u32 = 17664 B
#define SW   17664    // W tf32:   [32 h][28 k-pad]  u32 = 3584 B
#define SX2  21248    // xrow: [24][11][16] f32 = 16896 B  (row-side x)
#define SCG  38144    // cgs: 1332 f32 = 5328 B
#define SX1  43472    // xcol: [2][11][16] f32 = 1408 B    (chunk-side x)
#define SAS  44880    // As: ull[121][8] = 7744 B
#define SMEM_BYTES 52624

typedef unsigned long long ull;
typedef unsigned int u32;

// per-l transposed W scratch (d-major within each pair block)
__device__ float g_Wt[2045952];

__device__ __forceinline__ ull pack2(float v) {
    ull r; asm("mov.b64 %0, {%1, %1};" : "=l"(r) : "f"(v)); return r;
}
__device__ __forceinline__ ull mul2(ull a, ull b) {
    ull r; asm("mul.rn.f32x2 %0, %1, %2;" : "=l"(r) : "l"(a), "l"(b)); return r;
}
__device__ __forceinline__ ull fma2(ull a, ull b, ull c) {
    ull r; asm("fma.rn.f32x2 %0, %1, %2, %3;" : "=l"(r) : "l"(a), "l"(b), "l"(c)); return r;
}
__device__ __forceinline__ void unpack2(ull v, float& lo, float& hi) {
    asm("mov.b64 {%0, %1}, %2;" : "=f"(lo), "=f"(hi) : "l"(v));
}
__device__ __forceinline__ u32 tf32c(float f) {
    u32 r; asm("cvt.rna.tf32.f32 %0, %1;" : "=r"(r) : "f"(f)); return r;
}
__device__ __forceinline__ ull packu(u32 lo, u32 hi) {
    ull r; asm("mov.b64 %0, {%1, %2};" : "=l"(r) : "r"(lo), "r"(hi)); return r;
}

#define MMA_TF32(d, a, bb0, bb1) \
    asm volatile("mma.sync.aligned.m16n8k8.row.col.f32.tf32.tf32.f32 " \
        "{%0,%1,%2,%3}, {%4,%5,%6,%7}, {%8,%9}, {%0,%1,%2,%3};" \
        : "+f"((d)[0]), "+f"((d)[1]), "+f"((d)[2]), "+f"((d)[3]) \
        : "r"((a)[0]), "r"((a)[1]), "r"((a)[2]), "r"((a)[3]), "r"(bb0), "r"(bb1))

__device__ __forceinline__ const float* pick6(
    const float* a0, const float* a1, const float* a2,
    const float* a3, const float* a4, const float* a5, int l) {
    switch (l) {
        case 0: return a0; case 1: return a1; case 2: return a2;
        case 3: return a3; case 4: return a4; default: return a5;
    }
}

// Orientation: chunk side = larger-n side; phase-2 loop runs min(n1,n2).
// Both orientations load W with the SAME coalesced pattern: swapped items
// read from the pre-transposed g_Wt (d-major pair blocks).
template <int N>
__device__ __forceinline__ void run_pair(
    const float* __restrict__ Xc, char* smem,
    const float* __restrict__ Wl, int KIN, int koff,
    int nrow, int nchk, int sj, int cbase,
    float* __restrict__ out, int b0, int moff)
{
    constexpr int NT = 2 * N;        // number of n8 tiles over bm = 16*N
    constexpr int MS = (N + 3) / 4;
    const int tid  = threadIdx.x;
    const int lane = tid & 31;
    const int w    = tid >> 5;       // warp 0..7 (= k-group in cat build)
    const int bp   = tid & 7;        // batch pair lane (f32x2)
    const int rr   = tid >> 3;
    const int ms2  = rr & 3;         // mi slice in cat build
    const int mt     = w & 1;        // m16 tile over h (0..1)
    const int ntbase = w >> 1;       // n-tile base (stride 4)

    u32*  __restrict__ catT = (u32*)(smem + SCAT);
    u32*  __restrict__ WsU  = (u32*)(smem + SW);
    const ull* __restrict__ xr64 = (const ull*)(smem + SX2);
    const ull* __restrict__ xc64 = (const ull*)(smem + SX1);
    const float* __restrict__ cgs = (const float*)(smem + SCG);
    float* __restrict__ xcol = (float*)(smem + SX1);
    ull* __restrict__ As = (ull*)(smem + SAS);
    const unsigned nchku = (unsigned)nchk;
    const int xcstride = 24 * nchk;
    const int sd = 12 - sj;

    float acc[6][4];
#pragma unroll
    for (int j = 0; j < 6; ++j)
#pragma unroll
        for (int r = 0; r < 4; ++r) acc[j][r] = 0.f;

#pragma unroll 1
    for (int cc = 0; cc < NCHUNK; ++cc) {
        const int par = cc & 1;
        // ---- phase 1: W -> tf32 [h][28] (coalesced float2), A build, xcol staging ----
#pragma unroll
        for (int t = 0; t < 2; ++t) {
            const int i = tid + 256 * t;
            if (i < 384) {                       // 32 h x 12 float2
                const int h  = i / 12;
                const int kp = i - h * 12;
                const float2 wv = *reinterpret_cast<const float2*>(
                    Wl + h * KIN + koff + cc * 24 + kp * 2);
                WsU[h * 28 + kp * 2]     = tf32c(wv.x);
                WsU[h * 28 + kp * 2 + 1] = tf32c(wv.y);
            }
        }
        // A[mi][j][bp] = cg[mi; j (loop idx), der (chunk idx)] * xcol[cc][der][bp]
#pragma unroll
        for (int t = 0; t < 4; ++t) {
            const int s = rr + 32 * t;
            if (s < 121) {
                const int mi = s / 11;
                const int j  = s - mi * 11;
                if (j < nrow) {
                    const int der = mi + cbase - j;
                    const bool ok = ((unsigned)der < nchku);
                    const int dc = ok ? der : 0;
                    const float cgv = ok ? cgs[mi * 121 + j * sj + dc * sd] : 0.f;
                    const ull  xv  = xc64[par * 88 + dc * 8 + bp];
                    As[s * 8 + bp] = ok ? mul2(pack2(cgv), xv) : 0ull;
                }
            }
        }
        if (cc + 1 < NCHUNK && tid < 16 * nchk) {
            const int m = tid >> 4;
            const int b = tid & 15;
            xcol[(par ^ 1) * 176 + m * 16 + b] =
                Xc[(b0 + b) * xcstride + (cc + 1) * nchk + m];
        }
        __syncthreads();
        // ---- phase 2: cat build -> tf32 [k][bm], k=w*3+jj; loop = min(n1,n2) ----
        {
            ull bacc[3][MS];
#pragma unroll
            for (int j = 0; j < 3; ++j)
#pragma unroll
                for (int mj = 0; mj < MS; ++mj) bacc[j][mj] = 0ull;
#pragma unroll
            for (int j = 0; j < 11; ++j) {
                if (j >= nrow) break;             // CTA-uniform
                ull a[MS];
#pragma unroll
                for (int mj = 0; mj < MS; ++mj) {
                    const int mi = ms2 + 4 * mj;
                    if (mi < N) a[mj] = As[(mi * 11 + j) * 8 + bp];
                }
#pragma unroll
                for (int jj = 0; jj < 3; ++jj) {
                    const ull xv = xr64[(w * 3 + jj) * 88 + j * 8 + bp];
#pragma unroll
                    for (int mj = 0; mj < MS; ++mj) {
                        const int mi = ms2 + 4 * mj;
                        if (mi < N) bacc[jj][mj] = fma2(a[mj], xv, bacc[jj][mj]);
                    }
                }
            }
#pragma unroll
            for (int jj = 0; jj < 3; ++jj) {
                const int k = w * 3 + jj;
#pragma unroll
                for (int mj = 0; mj < MS; ++mj) {
                    const int mi = ms2 + 4 * mj;
                    if (mi < N) {
                        float lo, hi;
                        unpack2(bacc[jj][mj], lo, hi);
                        *reinterpret_cast<ull*>(catT + k * 184 + mi * 16 + 2 * bp) =
                            packu(tf32c(lo), tf32c(hi));
                    }
                }
            }
        }
        __syncthreads();
        // ---- phase 3: tf32 MMA GEMM: D[h][bm] += W[h][k] * cat[k][bm] ----
#pragma unroll
        for (int ks = 0; ks < 3; ++ks) {
            u32 a[4];
            {
                const int row = mt * 16 + (lane >> 2);
                const int col = ks * 8 + (lane & 3);
                a[0] = WsU[row * 28 + col];
                a[1] = WsU[(row + 8) * 28 + col];
                a[2] = WsU[row * 28 + col + 4];
                a[3] = WsU[(row + 8) * 28 + col + 4];
            }
            const int kr = ks * 8 + (lane & 3);
#pragma unroll
            for (int j = 0; j < 6; ++j) {
                const int nt = ntbase + 4 * j;
                if (nt < NT) {                    // warp-uniform
                    const int cb = nt * 8 + (lane >> 2);
                    const u32 b0v = catT[kr * 184 + cb];
                    const u32 b1v = catT[(kr + 4) * 184 + cb];
                    MMA_TF32(acc[j], a, b0v, b1v);
                }
            }
        }
        __syncthreads();
    }

    // ---- epilogue: fragments -> atomicAdd ----
#pragma unroll
    for (int j = 0; j < 6; ++j) {
        const int nt = ntbase + 4 * j;
        if (nt < NT) {
            const int hrow = mt * 16 + (lane >> 2);
            const int cb   = nt * 8 + 2 * (lane & 3);
#pragma unroll
            for (int r = 0; r < 4; ++r) {
                const int h  = hrow + ((r >> 1) << 3);
                const int bm = cb + (r & 1);
                const int b  = bm & 15;
                const int mi = bm >> 4;
                atomicAdd(out + (u32)(b0 + b) * 1152 + h * 36 + moff + mi, acc[j][r]);
            }
        }
    }
}

__global__ void __launch_bounds__(BLK, 4) cg_main(
    const float* __restrict__ X0, const float* __restrict__ X1, const float* __restrict__ X2,
    const float* __restrict__ X3, const float* __restrict__ X4, const float* __restrict__ X5,
    const float* __restrict__ W0, const float* __restrict__ W1, const float* __restrict__ W2,
    const float* __restrict__ W3, const float* __restrict__ W4, const float* __restrict__ W5,
    const float* __restrict__ cg, float* __restrict__ out)
{
    extern __shared__ char smem[];

    const int item = blockIdx.x >> 4;
    const int b0   = (blockIdx.x & 15) << 4;
    const int tid  = threadIdx.x;

    // decode work item: l ordered 5,4,3,2,1,0
    int l = 0, l1 = 0, l2 = 0, pidx = 0;
    {
        int cur = 0;
        bool done = false;
        for (int oi = 0; oi < 6 && !done; ++oi) {
            int L = 5 - oi;
            int pi = 0;
            for (int a = 0; a <= 5 && !done; ++a) {
                for (int b2 = 0; b2 <= 5; ++b2) {
                    int dd = a - b2; if (dd < 0) dd = -dd;
                    if (dd <= L && L <= a + b2) {
                        if (cur == item) { l = L; l1 = a; l2 = b2; pidx = pi; done = true; break; }
                        ++cur; ++pi;
                    }
                }
            }
        }
    }

    const int n1 = 2 * l1 + 1, n2 = 2 * l2 + 1, n = 2 * l + 1;
    int KIN, moff, woff;
    switch (l) {
        case 0: KIN = 3456;  moff = 0;  woff = 0;       break;
        case 1: KIN = 8640;  moff = 1;  woff = 110592;  break;
        case 2: KIN = 12096; moff = 4;  woff = 387072;  break;
        case 3: KIN = 13824; moff = 9;  woff = 774144;  break;
        case 4: KIN = 13824; moff = 16; woff = 1216512; break;
        default: KIN = 12096; moff = 25; woff = 1658880; break;
    }
    const float* Xa = pick6(X0, X1, X2, X3, X4, X5, l1);
    const float* Xb = pick6(X0, X1, X2, X3, X4, X5, l2);
    const float* Wl = pick6(W0, W1, W2, W3, W4, W5, l);
    const int koff = pidx * 576;

    // orientation: chunk side = larger n; row side (phase-2 loop) = min n.
    const int swap = (n2 > n1) ? 1 : 0;
    const float* Xrow = swap ? Xa : Xb;
    const float* Xchk = swap ? Xb : Xa;
    const int nrow = swap ? n1 : n2;
    const int nchk = swap ? n2 : n1;
    const int sj   = swap ? 11 : 1;
    const float* Wsel = swap ? (g_Wt + woff) : Wl;

    // row-side x tile: global (b,ch,m) -> smem [ch][m][b16]
    float* xrs = (float*)(smem + SX2);
    for (int i = tid; i < 16 * 24 * nrow; i += BLK) {
        int b = i / (24 * nrow);
        int r = i - b * 24 * nrow;
        int d = r / nrow;
        int m = r - d * nrow;
        xrs[(d * 11 + m) * 16 + b] = Xrow[(b0 + b) * 24 * nrow + r];
    }
    // cg slab
    float* cgs = (float*)(smem + SCG);
    const float* cgp = cg + ((l1 * 6 + l2) * 6 + l) * 1331;
    for (int i = tid; i < n * 121; i += BLK) cgs[i] = cgp[i];
    // chunk-side column cc=0 into buffer 0
    float* xcol = (float*)(smem + SX1);
    if (tid < 16 * nchk) {
        const int m = tid >> 4;
        const int b = tid & 15;
        xcol[m * 16 + b] = Xchk[(b0 + b) * (24 * nchk) + m];
    }
    __syncthreads();

    const int cbase = l1 + l2 - l;
    switch (l) {
        case 0: run_pair<1>(Xchk, smem, Wsel, KIN, koff, nrow, nchk, sj, cbase, out, b0, moff); break;
        case 1: run_pair<3>(Xchk, smem, Wsel, KIN, koff, nrow, nchk, sj, cbase, out, b0, moff); break;
        case 2: run_pair<5>(Xchk, smem, Wsel, KIN, koff, nrow, nchk, sj, cbase, out, b0, moff); break;
        case 3: run_pair<7>(Xchk, smem, Wsel, KIN, koff, nrow, nchk, sj, cbase, out, b0, moff); break;
        case 4: run_pair<9>(Xchk, smem, Wsel, KIN, koff, nrow, nchk, sj, cbase, out, b0, moff); break;
        default: run_pair<11>(Xchk, smem, Wsel, KIN, koff, nrow, nchk, sj, cbase, out, b0, moff); break;
    }
}

// single prep kernel: W transpose for all 6 l's + zero the output buffer.
// Wt[h][p*576+d*24+c] = W[h][p*576+c*24+d]
__global__ void prep_all(
    const float* __restrict__ W0, const float* __restrict__ W1, const float* __restrict__ W2,
    const float* __restrict__ W3, const float* __restrict__ W4, const float* __restrict__ W5,
    float* __restrict__ out)
{
    const int gi = blockIdx.x * 256 + threadIdx.x;
    if (gi < 294912) out[gi] = 0.f;     // zero output (256*32*36)
    if (gi >= 2045952) return;
    int l, base;
    if      (gi < 110592)  { l = 0; base = 0; }
    else if (gi < 387072)  { l = 1; base = 110592; }
    else if (gi < 774144)  { l = 2; base = 387072; }
    else if (gi < 1216512) { l = 3; base = 774144; }
    else if (gi < 1658880) { l = 4; base = 1216512; }
    else                   { l = 5; base = 1658880; }
    const int KIN = (l == 0) ? 3456 : (l == 1) ? 8640 : (l == 2) ? 12096
                  : (l == 3) ? 13824 : (l == 4) ? 13824 : 12096;
    const float* src = pick6(W0, W1, W2, W3, W4, W5, l);
    const int i = gi - base;
    const int h = i / KIN;
    const int t = i - h * KIN;
    const int p = t / 576;
    const int q = t - p * 576;
    const int d = q / 24;
    const int c = q - d * 24;
    g_Wt[gi] = src[h * KIN + p * 576 + c * 24 + d];
}

extern "C" void kernel_launch(void* const* d_in, const int* in_sizes, int n_in,
                              void* d_out, int out_size)
{
    const float* X[6];
    const float* W[6];
    for (int i = 0; i < 6; ++i) X[i] = (const float*)d_in[i];
    for (int i = 0; i < 6; ++i) W[i] = (const float*)d_in[6 + i];
    const float* cg = (const float*)d_in[12];
    float* out = (float*)d_out;

    prep_all<<<(2045952 + 255) / 256, 256>>>(W[0], W[1], W[2], W[3], W[4], W[5], out);

    cudaFuncSetAttribute(cg_main, cudaFuncAttributeMaxDynamicSharedMemorySize, SMEM_BYTES);
    cg_main<<<111 * 16, BLK, SMEM_BYTES>>>(
        X[0], X[1], X[2], X[3], X[4], X[5],
        W[0], W[1], W[2], W[3], W[4], W[5],
        cg, out);
}